// round 16
// baseline (speedup 1.0000x reference)
#include <cuda_runtime.h>
#include <cuda_fp16.h>
#include <cstdint>

// Problem constants
#define M_ROWS 16384      // 8 * 2048
#define D_IN   512
#define NB     8
#define KTOT   4608       // 512 (relu base) + 512*8 (bs+rbf)
#define N_OUT  512

// GEMM tiling (fp16 mma.sync m16n8k16, fp32 accum)
#define BM 128
#define BN 128
#define BK 96                       // fp16 K elements per stage (192 B/row)
#define NITER (KTOT / BK)           // 48
#define ASTRIDE 208                 // bytes per smem row: 192B data + 16B pad
#define A_BYTES (BM * ASTRIDE)      // 26624
#define B_BYTES (BN * ASTRIDE)      // 26624
#define STG_BYTES (A_BYTES + B_BYTES)           // 53248: A | B
#define SMEM_TOTAL (2 * STG_BYTES)              // 106496 (2 CTAs/SM = 208KB)

// Scratch: fp16 feature + weight matrices
__device__ __align__(16) __half g_F[(size_t)M_ROWS * KTOT];
__device__ __align__(16) __half g_W[(size_t)N_OUT * KTOT];

// ---------------------------------------------------------------------------
// PTX helpers — base sm_80-class features, valid on compute_100
// ---------------------------------------------------------------------------
__device__ __forceinline__ uint32_t smem_u32(const void* p) {
    uint32_t a;
    asm("{ .reg .u64 t; cvta.to.shared.u64 t, %1; cvt.u32.u64 %0, t; }" : "=r"(a) : "l"(p));
    return a;
}
__device__ __forceinline__ void cp_async16(uint32_t s, const void* g) {
    asm volatile("cp.async.cg.shared.global [%0], [%1], 16;" :: "r"(s), "l"(g));
}
#define CP_COMMIT() asm volatile("cp.async.commit_group;" ::: "memory")
#define CP_WAIT(n)  asm volatile("cp.async.wait_group %0;" :: "n"(n) : "memory")

__device__ __forceinline__ void ldsm4(uint32_t* r, uint32_t addr) {
    asm volatile("ldmatrix.sync.aligned.m8n8.x4.shared.b16 {%0,%1,%2,%3}, [%4];"
                 : "=r"(r[0]), "=r"(r[1]), "=r"(r[2]), "=r"(r[3]) : "r"(addr));
}
// fp16 mma m16n8k16, fp32 accumulate
__device__ __forceinline__ void hmma16816(float* c, const uint32_t* a,
                                          uint32_t b0, uint32_t b1) {
    asm volatile("mma.sync.aligned.m16n8k16.row.col.f32.f16.f16.f32 "
                 "{%0,%1,%2,%3}, {%4,%5,%6,%7}, {%8,%9}, {%0,%1,%2,%3};"
                 : "+f"(c[0]), "+f"(c[1]), "+f"(c[2]), "+f"(c[3])
                 : "r"(a[0]), "r"(a[1]), "r"(a[2]), "r"(a[3]), "r"(b0), "r"(b1));
}

// ---------------------------------------------------------------------------
// Kernel 0: convert weights to fp16, concat [base | spline]
// ---------------------------------------------------------------------------
__global__ void prep_kernel(const float* __restrict__ bw,
                            const float* __restrict__ sw) {
    int o = blockIdx.x;           // 0..511
    int t = threadIdx.x;          // 256 threads
    size_t rb = (size_t)o * KTOT;
    for (int k = t; k < D_IN; k += 256)
        g_W[rb + k] = __float2half(bw[o * D_IN + k]);
    const float* sp = sw + (size_t)o * (D_IN * NB);
    for (int k = t; k < D_IN * NB; k += 256)
        g_W[rb + D_IN + k] = __float2half(sp[k]);
}

// ---------------------------------------------------------------------------
// Kernel 1: layernorm + features -> fp16
// ---------------------------------------------------------------------------
__global__ void feat_kernel(const float* __restrict__ x,
                            const float* __restrict__ gamma,
                            const float* __restrict__ beta) {
    const int row = blockIdx.x;
    const int t   = threadIdx.x;        // 256 threads, 2 dims each
    const float* xr = x + (size_t)row * D_IN;

    float v0 = xr[t];
    float v1 = xr[t + 256];
    float s  = v0 + v1;
    float s2 = v0 * v0 + v1 * v1;
    #pragma unroll
    for (int off = 16; off; off >>= 1) {
        s  += __shfl_xor_sync(0xFFFFFFFFu, s,  off);
        s2 += __shfl_xor_sync(0xFFFFFFFFu, s2, off);
    }
    __shared__ float red[16];
    __shared__ float mu_s, rstd_s;
    int wid = t >> 5, lane = t & 31;
    if (lane == 0) { red[wid] = s; red[8 + wid] = s2; }
    __syncthreads();
    if (t == 0) {
        float ts = 0.f, ts2 = 0.f;
        #pragma unroll
        for (int i = 0; i < 8; i++) { ts += red[i]; ts2 += red[8 + i]; }
        float mu  = ts * (1.0f / 512.0f);
        float var = ts2 * (1.0f / 512.0f) - mu * mu;
        mu_s   = mu;
        rstd_s = rsqrtf(var + 1e-5f);
    }
    __syncthreads();
    const float mu = mu_s, rstd = rstd_s;

    size_t rb = (size_t)row * KTOT;
    const float H    = 3.0f / 5.0f;
    const float INVD = 7.0f / 3.0f;

    #pragma unroll
    for (int half = 0; half < 2; half++) {
        const int   d  = t + half * 256;
        const float xv = half ? v1 : v0;
        const float xn = (xv - mu) * rstd * gamma[d] + beta[d];

        g_F[rb + d] = __float2half(fmaxf(xn, 0.0f));

        // Cox-de Boor, uniform knots t_i = (i-3)*H - 1.5, i=0..11
        float b[11];
        #pragma unroll
        for (int i = 0; i < 11; i++) {
            float t0 = (float)(i - 3) * H - 1.5f;
            float t1 = (float)(i - 2) * H - 1.5f;
            b[i] = (xn >= t0 && xn < t1) ? 1.0f : 0.0f;
        }
        #pragma unroll
        for (int k = 1; k <= 3; k++) {
            const float inv = 1.0f / ((float)k * H);
            #pragma unroll
            for (int i = 0; i + k < 11; i++) {
                float ti   = (float)(i - 3) * H - 1.5f;
                float tik1 = (float)(i + k - 2) * H - 1.5f;
                float left  = (xn - ti) * inv;
                float right = (tik1 - xn) * inv;
                b[i] = left * b[i] + right * b[i + 1];
            }
        }

        __half oh[8];
        #pragma unroll
        for (int j = 0; j < 8; j++) {
            float g = -1.5f + (float)j * (3.0f / 7.0f);
            float u = (xn - g) * INVD;
            oh[j] = __float2half(b[j] + __expf(-u * u));
        }
        // 8 halfs = 16B; offset (512 + 8d)*2 bytes is 16B aligned
        *(uint4*)(&g_F[rb + D_IN + (size_t)d * NB]) = *(const uint4*)oh;
    }
}

// ---------------------------------------------------------------------------
// Dummy kernel: keeps ncu's -s 5 capture slot on the GEMM launch.
// ---------------------------------------------------------------------------
__global__ void align_kernel() {}

// ---------------------------------------------------------------------------
// Kernel 2: fp16 m16n8k16 GEMM, fp32 accumulators
// CTA: 128(M) x 128(N), 8 warps (4m x 2n), warp tile 32x64.
// BK=96 (48 iters): 33% fewer barrier pairs than BK=64 at identical
// crossbar/tensor balance. 2-stage cp.async pipeline, 2 CTAs/SM.
// ---------------------------------------------------------------------------
__global__ __launch_bounds__(256, 2) void gemm_kernel(float* __restrict__ C) {
    extern __shared__ char smem[];
    const uint32_t sbase = smem_u32(smem);
    const int t    = threadIdx.x;
    const int wid  = t >> 5;
    const int wm   = wid & 3;           // m sub-tile (0..3), 32 rows
    const int wn   = wid >> 2;          // n sub-tile (0..1), 64 cols
    const int lane = t & 31;
    const int m0   = blockIdx.y * BM;
    const int n0   = blockIdx.x * BN;

    const __half* A_g = g_F + (size_t)m0 * KTOT;
    const __half* B_g = g_W + (size_t)n0 * KTOT;

    // Per-lane ldmatrix base offsets (16-bit k16 fragment maps)
    const uint32_t a_off = (uint32_t)((((lane >> 3) & 1) * 8 + (lane & 7)) * ASTRIDE
                                      + (lane >> 4) * 16);
    const uint32_t b_off = (uint32_t)((((lane >> 4) & 1) * 8 + (lane & 7)) * ASTRIDE
                                      + ((lane >> 3) & 1) * 16);

    float acc[2][8][4];
    #pragma unroll
    for (int i = 0; i < 2; i++)
        #pragma unroll
        for (int j = 0; j < 8; j++)
            #pragma unroll
            for (int q = 0; q < 4; q++) acc[i][j][q] = 0.0f;

    // ---- stage loader: 12 cp.async of 16B per thread (256 threads) ----
    // A: 128 rows x 12 chunks = 1536 units; B: same.
    auto load_stage = [&](int st, int kc) {
        const uint32_t stage = sbase + st * STG_BYTES;
        #pragma unroll
        for (int r = 0; r < 6; r++) {
            int u = t + r * 256;               // 0..1535
            int row = u / 12, ch = u % 12;
            size_t go = (size_t)row * KTOT + kc + ch * 8;   // halfs
            uint32_t so = (uint32_t)(row * ASTRIDE + ch * 16);
            cp_async16(stage + so,           A_g + go);
            cp_async16(stage + A_BYTES + so, B_g + go);
        }
    };

    load_stage(0, 0);
    CP_COMMIT();

    for (int i = 0; i < NITER; i++) {
        if (i + 1 < NITER) {
            load_stage((i + 1) & 1, (i + 1) * BK);
            CP_COMMIT();
            CP_WAIT(1);
        } else {
            CP_WAIT(0);
        }
        __syncthreads();

        const uint32_t stage = sbase + (i & 1) * STG_BYTES;
        const uint32_t sA = stage;
        const uint32_t sB = stage + A_BYTES;
        const uint32_t awarp = (uint32_t)(wm * 32 * ASTRIDE);
        const uint32_t bwarp = (uint32_t)(wn * 64 * ASTRIDE);

        #pragma unroll
        for (int s = 0; s < 6; s++) {       // six k16 steps
            const uint32_t ks = (uint32_t)(s * 32);   // 16 fp16 = 32 bytes
            uint32_t a[2][4];
            #pragma unroll
            for (int im = 0; im < 2; im++)
                ldsm4(a[im], sA + awarp + (uint32_t)(im * 16 * ASTRIDE) + a_off + ks);
            // B fragments per 16-col group (bounds live registers)
            #pragma unroll
            for (int jj = 0; jj < 4; jj++) {
                uint32_t b[4];
                ldsm4(b, sB + bwarp + (uint32_t)(jj * 16 * ASTRIDE) + b_off + ks);
                #pragma unroll
                for (int im = 0; im < 2; im++)
                    #pragma unroll
                    for (int jh = 0; jh < 2; jh++) {
                        int j = jj * 2 + jh;
                        hmma16816(acc[im][j], a[im], b[jh * 2], b[jh * 2 + 1]);
                    }
            }
        }
        __syncthreads();   // all warps done with this stage before refill
    }

    // Writeout: row = m0 + wm*32 + im*16 + lane/4 (+8),
    //           col = n0 + wn*64 + j*8 + (lane%4)*2
    #pragma unroll
    for (int im = 0; im < 2; im++) {
        int r0 = m0 + wm * 32 + im * 16 + (lane >> 2);
        #pragma unroll
        for (int j = 0; j < 8; j++) {
            int cc = n0 + wn * 64 + j * 8 + (lane & 3) * 2;
            *(float2*)(C + (size_t)r0 * N_OUT + cc) =
                make_float2(acc[im][j][0], acc[im][j][1]);
            *(float2*)(C + (size_t)(r0 + 8) * N_OUT + cc) =
                make_float2(acc[im][j][2], acc[im][j][3]);
        }
    }
}

// ---------------------------------------------------------------------------
extern "C" void kernel_launch(void* const* d_in, const int* in_sizes, int n_in,
                              void* d_out, int out_size) {
    const float* x        = (const float*)d_in[0];
    const float* ln_gamma = (const float*)d_in[1];
    const float* ln_beta  = (const float*)d_in[2];
    const float* base_w   = (const float*)d_in[3];
    const float* spline_w = (const float*)d_in[4];
    (void)in_sizes; (void)n_in; (void)out_size;

    cudaFuncSetAttribute(gemm_kernel, cudaFuncAttributeMaxDynamicSharedMemorySize, SMEM_TOTAL);

    prep_kernel<<<N_OUT, 256>>>(base_w, spline_w);
    feat_kernel<<<M_ROWS, 256>>>(x, ln_gamma, ln_beta);
    align_kernel<<<1, 32>>>();   // keeps ncu -s 5 capture on the GEMM
    dim3 grid(N_OUT / BN, M_ROWS / BM);   // (4, 128) = 512 CTAs
    gemm_kernel<<<grid, 256, SMEM_TOTAL>>>((float*)d_out);
}

// round 17
// speedup vs baseline: 1.0155x; 1.0155x over previous
#include <cuda_runtime.h>
#include <cuda_fp16.h>
#include <cstdint>

// Problem constants
#define M_ROWS 16384      // 8 * 2048
#define D_IN   512
#define NB     8
#define KTOT   4608       // 512 (relu base) + 512*8 (bs+rbf)
#define N_OUT  512

// GEMM tiling (fp16 mma.sync m16n8k16, fp32 accum)
#define BM 128
#define BN 128
#define BK 64                       // fp16 K elements per stage (128 B/row)
#define NITER (KTOT / BK)           // 72
#define NSTAGE 3
#define ASTRIDE 144                 // bytes per smem row: 128B data + 16B pad
#define A_BYTES (BM * ASTRIDE)      // 18432
#define B_BYTES (BN * ASTRIDE)      // 18432
#define STG_BYTES (A_BYTES + B_BYTES)           // 36864: A | B
#define SMEM_TOTAL (NSTAGE * STG_BYTES)         // 110592 (2 CTAs/SM = 216KB)

// Scratch: fp16 feature + weight matrices
__device__ __align__(16) __half g_F[(size_t)M_ROWS * KTOT];
__device__ __align__(16) __half g_W[(size_t)N_OUT * KTOT];

// ---------------------------------------------------------------------------
// PTX helpers — base sm_80-class features, valid on compute_100
// ---------------------------------------------------------------------------
__device__ __forceinline__ uint32_t smem_u32(const void* p) {
    uint32_t a;
    asm("{ .reg .u64 t; cvta.to.shared.u64 t, %1; cvt.u32.u64 %0, t; }" : "=r"(a) : "l"(p));
    return a;
}
__device__ __forceinline__ void cp_async16(uint32_t s, const void* g) {
    asm volatile("cp.async.cg.shared.global [%0], [%1], 16;" :: "r"(s), "l"(g));
}
#define CP_COMMIT() asm volatile("cp.async.commit_group;" ::: "memory")
#define CP_WAIT(n)  asm volatile("cp.async.wait_group %0;" :: "n"(n) : "memory")

__device__ __forceinline__ void ldsm4(uint32_t* r, uint32_t addr) {
    asm volatile("ldmatrix.sync.aligned.m8n8.x4.shared.b16 {%0,%1,%2,%3}, [%4];"
                 : "=r"(r[0]), "=r"(r[1]), "=r"(r[2]), "=r"(r[3]) : "r"(addr));
}
// fp16 mma m16n8k16, fp32 accumulate
__device__ __forceinline__ void hmma16816(float* c, const uint32_t* a,
                                          uint32_t b0, uint32_t b1) {
    asm volatile("mma.sync.aligned.m16n8k16.row.col.f32.f16.f16.f32 "
                 "{%0,%1,%2,%3}, {%4,%5,%6,%7}, {%8,%9}, {%0,%1,%2,%3};"
                 : "+f"(c[0]), "+f"(c[1]), "+f"(c[2]), "+f"(c[3])
                 : "r"(a[0]), "r"(a[1]), "r"(a[2]), "r"(a[3]), "r"(b0), "r"(b1));
}

// ---------------------------------------------------------------------------
// Kernel 0: convert weights to fp16, concat [base | spline]
// ---------------------------------------------------------------------------
__global__ void prep_kernel(const float* __restrict__ bw,
                            const float* __restrict__ sw) {
    int o = blockIdx.x;           // 0..511
    int t = threadIdx.x;          // 256 threads
    size_t rb = (size_t)o * KTOT;
    for (int k = t; k < D_IN; k += 256)
        g_W[rb + k] = __float2half(bw[o * D_IN + k]);
    const float* sp = sw + (size_t)o * (D_IN * NB);
    for (int k = t; k < D_IN * NB; k += 256)
        g_W[rb + D_IN + k] = __float2half(sp[k]);
}

// ---------------------------------------------------------------------------
// Kernel 1: layernorm + features -> fp16
// ---------------------------------------------------------------------------
__global__ void feat_kernel(const float* __restrict__ x,
                            const float* __restrict__ gamma,
                            const float* __restrict__ beta) {
    const int row = blockIdx.x;
    const int t   = threadIdx.x;        // 256 threads, 2 dims each
    const float* xr = x + (size_t)row * D_IN;

    float v0 = xr[t];
    float v1 = xr[t + 256];
    float s  = v0 + v1;
    float s2 = v0 * v0 + v1 * v1;
    #pragma unroll
    for (int off = 16; off; off >>= 1) {
        s  += __shfl_xor_sync(0xFFFFFFFFu, s,  off);
        s2 += __shfl_xor_sync(0xFFFFFFFFu, s2, off);
    }
    __shared__ float red[16];
    __shared__ float mu_s, rstd_s;
    int wid = t >> 5, lane = t & 31;
    if (lane == 0) { red[wid] = s; red[8 + wid] = s2; }
    __syncthreads();
    if (t == 0) {
        float ts = 0.f, ts2 = 0.f;
        #pragma unroll
        for (int i = 0; i < 8; i++) { ts += red[i]; ts2 += red[8 + i]; }
        float mu  = ts * (1.0f / 512.0f);
        float var = ts2 * (1.0f / 512.0f) - mu * mu;
        mu_s   = mu;
        rstd_s = rsqrtf(var + 1e-5f);
    }
    __syncthreads();
    const float mu = mu_s, rstd = rstd_s;

    size_t rb = (size_t)row * KTOT;
    const float H    = 3.0f / 5.0f;
    const float INVD = 7.0f / 3.0f;

    #pragma unroll
    for (int half = 0; half < 2; half++) {
        const int   d  = t + half * 256;
        const float xv = half ? v1 : v0;
        const float xn = (xv - mu) * rstd * gamma[d] + beta[d];

        g_F[rb + d] = __float2half(fmaxf(xn, 0.0f));

        // Cox-de Boor, uniform knots t_i = (i-3)*H - 1.5, i=0..11
        float b[11];
        #pragma unroll
        for (int i = 0; i < 11; i++) {
            float t0 = (float)(i - 3) * H - 1.5f;
            float t1 = (float)(i - 2) * H - 1.5f;
            b[i] = (xn >= t0 && xn < t1) ? 1.0f : 0.0f;
        }
        #pragma unroll
        for (int k = 1; k <= 3; k++) {
            const float inv = 1.0f / ((float)k * H);
            #pragma unroll
            for (int i = 0; i + k < 11; i++) {
                float ti   = (float)(i - 3) * H - 1.5f;
                float tik1 = (float)(i + k - 2) * H - 1.5f;
                float left  = (xn - ti) * inv;
                float right = (tik1 - xn) * inv;
                b[i] = left * b[i] + right * b[i + 1];
            }
        }

        __half oh[8];
        #pragma unroll
        for (int j = 0; j < 8; j++) {
            float g = -1.5f + (float)j * (3.0f / 7.0f);
            float u = (xn - g) * INVD;
            oh[j] = __float2half(b[j] + __expf(-u * u));
        }
        // 8 halfs = 16B; offset (512 + 8d)*2 bytes is 16B aligned
        *(uint4*)(&g_F[rb + D_IN + (size_t)d * NB]) = *(const uint4*)oh;
    }
}

// ---------------------------------------------------------------------------
// Dummy kernel: keeps ncu's -s 5 capture slot on the GEMM launch.
// ---------------------------------------------------------------------------
__global__ void align_kernel() {}

// ---------------------------------------------------------------------------
// Kernel 2: fp16 m16n8k16 GEMM, fp32 accumulators
// CTA: 128(M) x 128(N), 8 warps (4m x 2n), warp tile 32x64, BK=64.
// 3-stage cp.async ring, ONE __syncthreads per iteration:
//   wait(stage i) -> sync -> issue(stage i+2) -> compute(stage i)
// Buffer (i+2)%3 == (i-1)%3 was read in iter i-1; the sync orders that.
// Two compute-iterations of cp.async latency cover. 2 CTAs/SM.
// ---------------------------------------------------------------------------
__global__ __launch_bounds__(256, 2) void gemm_kernel(float* __restrict__ C) {
    extern __shared__ char smem[];
    const uint32_t sbase = smem_u32(smem);
    const int t    = threadIdx.x;
    const int wid  = t >> 5;
    const int wm   = wid & 3;           // m sub-tile (0..3), 32 rows
    const int wn   = wid >> 2;          // n sub-tile (0..1), 64 cols
    const int lane = t & 31;
    const int m0   = blockIdx.y * BM;
    const int n0   = blockIdx.x * BN;

    const __half* A_g = g_F + (size_t)m0 * KTOT;
    const __half* B_g = g_W + (size_t)n0 * KTOT;

    // Per-lane ldmatrix base offsets (16-bit k16 fragment maps)
    const uint32_t a_off = (uint32_t)((((lane >> 3) & 1) * 8 + (lane & 7)) * ASTRIDE
                                      + (lane >> 4) * 16);
    const uint32_t b_off = (uint32_t)((((lane >> 4) & 1) * 8 + (lane & 7)) * ASTRIDE
                                      + ((lane >> 3) & 1) * 16);

    float acc[2][8][4];
    #pragma unroll
    for (int i = 0; i < 2; i++)
        #pragma unroll
        for (int j = 0; j < 8; j++)
            #pragma unroll
            for (int q = 0; q < 4; q++) acc[i][j][q] = 0.0f;

    // ---- stage loader: 8 cp.async of 16B per thread (256 threads) ----
    // A: 128 rows x 8 chunks = 1024 units; B: 128 x 8 = 1024 units.
    // Power-of-2 addressing only (R16 lesson: div/mod in the loader costs issue).
    auto load_stage = [&](int st, int kc) {
        const uint32_t stage = sbase + (uint32_t)st * STG_BYTES;
        #pragma unroll
        for (int r = 0; r < 4; r++) {
            int u = t + r * 256;               // 0..1023
            int row = u >> 3, ch = u & 7;
            size_t go = (size_t)row * KTOT + kc + ch * 8;   // halfs
            uint32_t so = (uint32_t)(row * ASTRIDE + ch * 16);
            cp_async16(stage + so,           A_g + go);
            cp_async16(stage + A_BYTES + so, B_g + go);
        }
    };

    // Prologue: fill stages 0 and 1
    load_stage(0, 0);
    CP_COMMIT();
    load_stage(1, BK);
    CP_COMMIT();

    int stage_rd = 0;      // stage holding K-chunk i
    int stage_wr = 2;      // stage to fill with K-chunk i+2

    for (int i = 0; i < NITER; i++) {
        // Stage i ready (leave the newest group in flight when one exists)
        if (i == NITER - 1) { CP_WAIT(0); } else { CP_WAIT(1); }
        // Single barrier: (a) stage-i loads visible; (b) all warps finished
        // reading stage i-1 (== stage_wr) in the previous iteration.
        __syncthreads();

        if (i + 2 < NITER) {
            load_stage(stage_wr, (i + 2) * BK);
            CP_COMMIT();
        }

        const uint32_t stage = sbase + (uint32_t)stage_rd * STG_BYTES;
        const uint32_t sA = stage;
        const uint32_t sB = stage + A_BYTES;
        const uint32_t awarp = (uint32_t)(wm * 32 * ASTRIDE);
        const uint32_t bwarp = (uint32_t)(wn * 64 * ASTRIDE);

        #pragma unroll
        for (int s = 0; s < 4; s++) {       // four k16 steps
            const uint32_t ks = (uint32_t)(s * 32);   // 16 fp16 = 32 bytes
            uint32_t a[2][4];
            #pragma unroll
            for (int im = 0; im < 2; im++)
                ldsm4(a[im], sA + awarp + (uint32_t)(im * 16 * ASTRIDE) + a_off + ks);
            // B fragments per 16-col group (bounds live registers)
            #pragma unroll
            for (int jj = 0; jj < 4; jj++) {
                uint32_t b[4];
                ldsm4(b, sB + bwarp + (uint32_t)(jj * 16 * ASTRIDE) + b_off + ks);
                #pragma unroll
                for (int im = 0; im < 2; im++)
                    #pragma unroll
                    for (int jh = 0; jh < 2; jh++) {
                        int j = jj * 2 + jh;
                        hmma16816(acc[im][j], a[im], b[jh * 2], b[jh * 2 + 1]);
                    }
            }
        }

        stage_rd = (stage_rd == NSTAGE - 1) ? 0 : stage_rd + 1;
        stage_wr = (stage_wr == NSTAGE - 1) ? 0 : stage_wr + 1;
    }

    // Writeout: row = m0 + wm*32 + im*16 + lane/4 (+8),
    //           col = n0 + wn*64 + j*8 + (lane%4)*2
    #pragma unroll
    for (int im = 0; im < 2; im++) {
        int r0 = m0 + wm * 32 + im * 16 + (lane >> 2);
        #pragma unroll
        for (int j = 0; j < 8; j++) {
            int cc = n0 + wn * 64 + j * 8 + (lane & 3) * 2;
            *(float2*)(C + (size_t)r0 * N_OUT + cc) =
                make_float2(acc[im][j][0], acc[im][j][1]);
            *(float2*)(C + (size_t)(r0 + 8) * N_OUT + cc) =
                make_float2(acc[im][j][2], acc[im][j][3]);
        }
    }
}

// ---------------------------------------------------------------------------
extern "C" void kernel_launch(void* const* d_in, const int* in_sizes, int n_in,
                              void* d_out, int out_size) {
    const float* x        = (const float*)d_in[0];
    const float* ln_gamma = (const float*)d_in[1];
    const float* ln_beta  = (const float*)d_in[2];
    const float* base_w   = (const float*)d_in[3];
    const float* spline_w = (const float*)d_in[4];
    (void)in_sizes; (void)n_in; (void)out_size;

    cudaFuncSetAttribute(gemm_kernel, cudaFuncAttributeMaxDynamicSharedMemorySize, SMEM_TOTAL);

    prep_kernel<<<N_OUT, 256>>>(base_w, spline_w);
    feat_kernel<<<M_ROWS, 256>>>(x, ln_gamma, ln_beta);
    align_kernel<<<1, 32>>>();   // keeps ncu -s 5 capture on the GEMM
    dim3 grid(N_OUT / BN, M_ROWS / BM);   // (4, 128) = 512 CTAs
    gemm_kernel<<<grid, 256, SMEM_TOTAL>>>((float*)d_out);
}